// round 17
// baseline (speedup 1.0000x reference)
#include <cuda_runtime.h>
#include <cuda_fp16.h>
#include <cstdint>

// CIN via mma.sync (base-ISA tensor cores).
// out[r,j] = sum_{h,m} xl[r,h]*x0[r,m]*W[h*32+m,j]; r = b*16+d.
// R17: R16 + l2_reduce deleted: out[:,256:384] initialized to 16*b2 by extra
//      wprep blocks; l2_gemm accumulates split-K contributions with
//      atomicAdd (REDG.F32) directly into out. 8.4MB partial buffer gone.

namespace {
constexpr int RTOT = 16384;           // 1024 batches * 16 emb rows
constexpr int NOUT = 128;
constexpr int OUTW = 384;
constexpr int TM   = 64;              // rows per CTA (= 4 batches)
constexpr int NCTA = RTOT / TM;       // 256
constexpr int NTHR = 256;
constexpr int KC   = 128;             // K per chunk
constexpr int CHUNK_BYTES = 128 * KC * 2;   // 32768
constexpr int NCH_TOT = 8 + 32;       // L0 + L1 chunks

// SMEM layout for cin01 (bytes)
constexpr int OFF_B    = 0;                        // 2 stages x 32768
constexpr int OFF_X0   = 65536;                    // float[64][33] = 8448
constexpr int OFF_BIAS = 73984;                    // 2 x 128 floats = 1024
constexpr int OFF_XLH  = 75008;                    // half[64][132] = 16896
constexpr int OFF_MBAR = 91904;                    // 2 x 8B
constexpr int SMEM_TOTAL = 91920;
// layer-1 epilogue reuses [OFF_B..): float[64][129] xl2 stash (33024 B)

// SMEM layout for l2_gemm (bytes)
constexpr int OFF2_A    = 0;                       // 2 stages x 16384
constexpr int OFF2_B    = 32768;                   // 2 stages x 32768
constexpr int OFF2_MBAR = 98304;                   // 2 x 8B
constexpr int SMEM2_TOTAL = 98320;
}

// device-global scratch (allocation-free rule)
// g_Wt: per layer, chunk-major pre-swizzled byte image:
//   byte off = c*32768 + (kk>>6)*16384 + j*128 + (((kk&63)*2) ^ ((j&7)<<4))
__device__ __align__(128) __half g_Wt[128 * (1024 + 4096 + 4096)];
__device__ __align__(128) float  g_xlB[RTOT * NOUT];  // C2 fp16 swizzled image

// ---------------- helpers ----------------
__device__ __forceinline__ uint32_t smem_u32(const void* p) {
    uint32_t a;
    asm("{ .reg .u64 t; cvta.to.shared.u64 t, %1; cvt.u32.u64 %0, t; }" : "=r"(a) : "l"(p));
    return a;
}
__device__ __forceinline__ void ldsm4(uint32_t* r, uint32_t addr) {
    asm volatile("ldmatrix.sync.aligned.m8n8.x4.shared.b16 {%0,%1,%2,%3}, [%4];"
                 : "=r"(r[0]), "=r"(r[1]), "=r"(r[2]), "=r"(r[3]) : "r"(addr));
}
__device__ __forceinline__ void mma16816(float* c, const uint32_t* a, const uint32_t* b) {
    asm volatile("mma.sync.aligned.m16n8k16.row.col.f32.f16.f16.f32 "
                 "{%0,%1,%2,%3}, {%4,%5,%6,%7}, {%8,%9}, {%0,%1,%2,%3};"
                 : "+f"(c[0]), "+f"(c[1]), "+f"(c[2]), "+f"(c[3])
                 : "r"(a[0]), "r"(a[1]), "r"(a[2]), "r"(a[3]), "r"(b[0]), "r"(b[1]));
}
__device__ __forceinline__ uint32_t h2u(__half2 h) {
    return *reinterpret_cast<uint32_t*>(&h);
}
#define MBAR_INIT(mb, n) \
    asm volatile("mbarrier.init.shared.b64 [%0], %1;" :: "r"((uint32_t)(mb)), "r"((uint32_t)(n)) : "memory")
#define MBAR_EXPECT_TX(mb, tx) \
    asm volatile("mbarrier.arrive.expect_tx.shared.b64 _, [%0], %1;" :: "r"((uint32_t)(mb)), "r"((uint32_t)(tx)) : "memory")
#define MBAR_WAIT(mb, ph) \
    asm volatile("{\n\t.reg .pred p;\n\t" \
        "WL_%=:\n\t" \
        "mbarrier.try_wait.parity.shared.b64 p, [%0], %1;\n\t" \
        "@!p bra WL_%=;\n\t}" :: "r"((uint32_t)(mb)), "r"((uint32_t)(ph)) : "memory")
#define BULK_CP(dst, src, bytes, mb) \
    asm volatile("cp.async.bulk.shared::cta.global.mbarrier::complete_tx::bytes [%0], [%1], %2, [%3];" \
                 :: "r"((uint32_t)(dst)), "l"(src), "r"((uint32_t)(bytes)), "r"((uint32_t)(mb)) : "memory")

// -------- W -> chunk-major pre-swizzled fp16 image + out[:,256:384) init ----
// blocks 0..31 -> L0, 32..159 -> L1, 160..287 -> L2, 288..415 -> out init
__global__ void wprep_all(const float* __restrict__ W0,
                          const float* __restrict__ W1,
                          const float* __restrict__ W2,
                          const float* __restrict__ b2,
                          float* __restrict__ out) {
    const int b = blockIdx.x;
    if (b >= 288) {   // init out cols [256,384) with 16*b2
        const int blk = b - 288;                     // 0..127 -> 8 batches each
        const int t = threadIdx.x;
        const int bat = blk * 8 + (t >> 5);
        const int j4 = (t & 31) * 4;
        float4 v = make_float4(16.f * b2[j4], 16.f * b2[j4 + 1],
                               16.f * b2[j4 + 2], 16.f * b2[j4 + 3]);
        *reinterpret_cast<float4*>(&out[(size_t)bat * OUTW + 256 + j4]) = v;
        return;
    }

    const float* W;
    char* Wt;
    int kb;
    if (b < 32)       { W = W0; Wt = reinterpret_cast<char*>(g_Wt);          kb = b; }
    else if (b < 160) { W = W1; Wt = reinterpret_cast<char*>(g_Wt + 131072); kb = b - 32; }
    else              { W = W2; Wt = reinterpret_cast<char*>(g_Wt + 655360); kb = b - 160; }

    __shared__ float s[32][129];
    const int k0 = kb * 32;
    const int t  = threadIdx.x;
#pragma unroll
    for (int i = 0; i < 16; i++) {
        int idx = t + i * 256;
        int kk = idx >> 7, j = idx & 127;
        s[kk][j] = W[(size_t)(k0 + kk) * 128 + j];
    }
    __syncthreads();
    const int j = t >> 1, hb = t & 1;
    const int c = k0 >> 7;
#pragma unroll
    for (int r = 0; r < 2; r++) {
        uint32_t w[4];
        const int kk = (k0 & 127) + hb * 16 + r * 8;
#pragma unroll
        for (int e = 0; e < 4; e++) {
            int kl = hb * 16 + r * 8 + e * 2;
            __half2 h2 = __floats2half2_rn(s[kl][j], s[kl + 1][j]);
            w[e] = *reinterpret_cast<uint32_t*>(&h2);
        }
        size_t off = (size_t)c * 32768 + (kk >> 6) * 16384 + j * 128
                   + (((uint32_t)(kk & 63) * 2) ^ ((uint32_t)(j & 7) << 4));
        *reinterpret_cast<uint4*>(Wt + off) = make_uint4(w[0], w[1], w[2], w[3]);
    }
}

// ---------------- fused layers 0+1 kernel ----------------
__global__ __launch_bounds__(NTHR, 2)
void cin01(const float* __restrict__ inputs,
           const float* __restrict__ b0,
           const float* __restrict__ b1,
           float* __restrict__ out)
{
    extern __shared__ char smem[];
    const uint32_t sb = smem_u32(smem);

    const int tid  = threadIdx.x;
    const int wid  = tid >> 5;
    const int lane = tid & 31;
    const int blk  = blockIdx.x;

    const char* Wt0 = reinterpret_cast<const char*>(g_Wt);
    const char* Wt1 = reinterpret_cast<const char*>(g_Wt + 131072);

    auto chunk_src = [&](int i) -> const char* {
        return (i < 8) ? Wt0 + (size_t)i * CHUNK_BYTES
                       : Wt1 + (size_t)(i - 8) * CHUNK_BYTES;
    };
    auto issue = [&](int i) {
        if (tid == 0) {
            MBAR_EXPECT_TX(sb + OFF_MBAR + 8 * (i & 1), CHUNK_BYTES);
            BULK_CP(sb + OFF_B + (i & 1) * 32768, chunk_src(i),
                    CHUNK_BYTES, sb + OFF_MBAR + 8 * (i & 1));
        }
    };

    if (tid == 0) {
        MBAR_INIT(sb + OFF_MBAR + 0, 1);
        MBAR_INIT(sb + OFF_MBAR + 8, 1);
    }
    __syncthreads();
    issue(0);

    // ---- x0 tile (4 batches, contiguous 2048 floats) + both biases ----
    {
        const float* src = inputs + (size_t)blk * 2048;
        float* x0sw = reinterpret_cast<float*>(smem + OFF_X0);
#pragma unroll
        for (int i = 0; i < 8; i++) {
            int idx = tid + i * NTHR;
            int bb = idx >> 9, m = (idx >> 4) & 31, d = idx & 15;
            x0sw[(bb * 16 + d) * 33 + m] = src[idx];
        }
        float* biass = reinterpret_cast<float*>(smem + OFF_BIAS);
        if (tid < 128)      biass[tid] = b0[tid];
        else                biass[tid] = b1[tid - 128];
    }
    __syncthreads();

    // ---- per-thread x0 fragment registers ----
    const int mg = wid >> 2, ng = wid & 3;
    const int rlow = lane >> 2, c0 = (lane & 3) * 2;
    const int g = lane >> 3;
    const float* x0s = reinterpret_cast<const float*>(smem + OFF_X0);
    __half2 x0p[4][4];
    int rowv[4];
#pragma unroll
    for (int rr = 0; rr < 4; rr++) {
        const int mt = rr >> 1, s = rr & 1;
        const int row = mg * 32 + mt * 16 + rlow + s * 8;
        rowv[rr] = row;
#pragma unroll
        for (int j = 0; j < 4; j++)
            x0p[rr][j] = __floats2half2_rn(x0s[row * 33 + c0 + 8 * j],
                                           x0s[row * 33 + c0 + 8 * j + 1]);
    }

    float acc[2][4][4];
#pragma unroll
    for (int mt = 0; mt < 2; mt++)
#pragma unroll
        for (int nt = 0; nt < 4; nt++)
#pragma unroll
            for (int e = 0; e < 4; e++) acc[mt][nt][e] = 0.f;

    const int br0 = ng * 32 + (g >> 1) * 8 + (lane & 7);
    const int br1 = br0 + 16;
    auto baddr = [&](uint32_t bbase, int br, int ks) {
        const int bk = ks * 16 + (g & 1) * 8;
        return bbase + (bk >> 6) * 16384 + br * 128
             + (((uint32_t)(bk & 63) * 2) ^ ((br & 7) << 4));
    };

    // compute one 128-K chunk given xl2 broadcast regs
    auto do_chunk = [&](int i, __half2 xl2[4][4]) {
        const uint32_t bbase = sb + OFF_B + (i & 1) * 32768;
        uint32_t bcur[8], bnxt[8];
        ldsm4(bcur,     baddr(bbase, br0, 0));
        ldsm4(bcur + 4, baddr(bbase, br1, 0));
#pragma unroll
        for (int ks = 0; ks < 8; ks++) {
            if (ks < 7) {
                ldsm4(bnxt,     baddr(bbase, br0, ks + 1));
                ldsm4(bnxt + 4, baddr(bbase, br1, ks + 1));
            }
            const int hh = ks >> 1;
            const int jb = (ks & 1) * 2;
            uint32_t afr[2][4];
#pragma unroll
            for (int mt = 0; mt < 2; mt++) {
                afr[mt][0] = h2u(__hmul2(x0p[mt * 2 + 0][jb],     xl2[mt * 2 + 0][hh]));
                afr[mt][1] = h2u(__hmul2(x0p[mt * 2 + 1][jb],     xl2[mt * 2 + 1][hh]));
                afr[mt][2] = h2u(__hmul2(x0p[mt * 2 + 0][jb + 1], xl2[mt * 2 + 0][hh]));
                afr[mt][3] = h2u(__hmul2(x0p[mt * 2 + 1][jb + 1], xl2[mt * 2 + 1][hh]));
            }
#pragma unroll
            for (int mt = 0; mt < 2; mt++)
#pragma unroll
                for (int nt = 0; nt < 4; nt++)
                    mma16816(acc[mt][nt], afr[mt], bcur + nt * 2);
#pragma unroll
            for (int e = 0; e < 8; e++) bcur[e] = bnxt[e];
        }
    };

    __half* xlh = reinterpret_cast<__half*>(smem + OFF_XLH);   // [64][132]
    const float* biass = reinterpret_cast<const float*>(smem + OFF_BIAS);

    // ================= layer 0: chunks 0..7 =================
    for (int i = 0; i < 8; i++) {
        MBAR_WAIT(sb + OFF_MBAR + 8 * (i & 1), (i >> 1) & 1);
        __syncthreads();
        if (i + 1 < NCH_TOT) issue(i + 1);

        __half2 xl2[4][4];
#pragma unroll
        for (int rr = 0; rr < 4; rr++)
#pragma unroll
            for (int hh = 0; hh < 4; hh++)
                xl2[rr][hh] = __half2half2(__float2half_rn(x0s[rowv[rr] * 33 + i * 4 + hh]));
        do_chunk(i, xl2);
    }

    // ---- layer 0 epilogue: relu -> fp16 stash; d-sum -> out cols [0,128) ----
#pragma unroll
    for (int mt = 0; mt < 2; mt++) {
        const int batch = blk * 4 + mg * 2 + mt;
        const int rl = mg * 32 + mt * 16 + rlow;
#pragma unroll
        for (int nt = 0; nt < 4; nt++) {
            const int j0 = ng * 32 + nt * 8 + (lane & 3) * 2;
            const float bb0 = biass[j0], bb1 = biass[j0 + 1];
            float v0 = fmaxf(acc[mt][nt][0] + bb0, 0.f);
            float v1 = fmaxf(acc[mt][nt][1] + bb1, 0.f);
            float v2 = fmaxf(acc[mt][nt][2] + bb0, 0.f);
            float v3 = fmaxf(acc[mt][nt][3] + bb1, 0.f);
            *reinterpret_cast<__half2*>(&xlh[rl * 132 + j0])       = __floats2half2_rn(v0, v1);
            *reinterpret_cast<__half2*>(&xlh[(rl + 8) * 132 + j0]) = __floats2half2_rn(v2, v3);
            float s0 = v0 + v2, s1 = v1 + v3;
            s0 += __shfl_xor_sync(0xffffffffu, s0, 4);
            s1 += __shfl_xor_sync(0xffffffffu, s1, 4);
            s0 += __shfl_xor_sync(0xffffffffu, s0, 8);
            s1 += __shfl_xor_sync(0xffffffffu, s1, 8);
            s0 += __shfl_xor_sync(0xffffffffu, s0, 16);
            s1 += __shfl_xor_sync(0xffffffffu, s1, 16);
            if (lane < 4) {
                float* dst = out + (size_t)batch * OUTW + ng * 32 + nt * 8 + lane * 2;
                dst[0] = s0;
                dst[1] = s1;
            }
        }
    }
    __syncthreads();   // xlh stash visible to all warps

#pragma unroll
    for (int mt = 0; mt < 2; mt++)
#pragma unroll
        for (int nt = 0; nt < 4; nt++)
#pragma unroll
            for (int e = 0; e < 4; e++) acc[mt][nt][e] = 0.f;

    // ================= layer 1: chunks 8..39 =================
    for (int i = 8; i < NCH_TOT; i++) {
        MBAR_WAIT(sb + OFF_MBAR + 8 * (i & 1), (i >> 1) & 1);
        __syncthreads();
        if (i + 1 < NCH_TOT) issue(i + 1);

        const int c1 = i - 8;
        __half2 xl2[4][4];
#pragma unroll
        for (int rr = 0; rr < 4; rr++)
#pragma unroll
            for (int hh = 0; hh < 4; hh++)
                xl2[rr][hh] = __half2half2(xlh[rowv[rr] * 132 + c1 * 4 + hh]);
        do_chunk(i, xl2);
    }

    // ---- layer 1 epilogue: fp32 stash in OFF_B; out cols [128,256); gram ----
    float* xl2s = reinterpret_cast<float*>(smem + OFF_B);  // [64][129]
    __syncthreads();                                       // B stages consumed
#pragma unroll
    for (int mt = 0; mt < 2; mt++) {
        const int batch = blk * 4 + mg * 2 + mt;
        const int rl = mg * 32 + mt * 16 + rlow;
#pragma unroll
        for (int nt = 0; nt < 4; nt++) {
            const int j0 = ng * 32 + nt * 8 + (lane & 3) * 2;
            const float bb0 = biass[128 + j0], bb1 = biass[128 + j0 + 1];
            float v0 = fmaxf(acc[mt][nt][0] + bb0, 0.f);
            float v1 = fmaxf(acc[mt][nt][1] + bb1, 0.f);
            float v2 = fmaxf(acc[mt][nt][2] + bb0, 0.f);
            float v3 = fmaxf(acc[mt][nt][3] + bb1, 0.f);
            xl2s[rl * 129 + j0]           = v0;
            xl2s[rl * 129 + j0 + 1]       = v1;
            xl2s[(rl + 8) * 129 + j0]     = v2;
            xl2s[(rl + 8) * 129 + j0 + 1] = v3;
            float s0 = v0 + v2, s1 = v1 + v3;
            s0 += __shfl_xor_sync(0xffffffffu, s0, 4);
            s1 += __shfl_xor_sync(0xffffffffu, s1, 4);
            s0 += __shfl_xor_sync(0xffffffffu, s0, 8);
            s1 += __shfl_xor_sync(0xffffffffu, s1, 8);
            s0 += __shfl_xor_sync(0xffffffffu, s0, 16);
            s1 += __shfl_xor_sync(0xffffffffu, s1, 16);
            if (lane < 4) {
                float* dst = out + (size_t)batch * OUTW + 128 + ng * 32 + nt * 8 + lane * 2;
                dst[0] = s0;
                dst[1] = s1;
            }
        }
    }
    __syncthreads();                                   // xl2s complete

    // inline gram: C2_b[h,m] = sum_d xl2[b,d,h] * x0[b,d,m] -> fp16 image
    {
        char* img = reinterpret_cast<char*>(g_xlB);
#pragma unroll
        for (int p = 0; p < 2; p++) {
            const int pid = tid + p * 256;
            const int bb = pid >> 7, h = pid & 127;
            float a32[32];
#pragma unroll
            for (int m = 0; m < 32; m++) a32[m] = 0.f;
#pragma unroll
            for (int d = 0; d < 16; d++) {
                const int rl = bb * 16 + d;
                const float xv = xl2s[rl * 129 + h];
                const float* xr = x0s + rl * 33;
#pragma unroll
                for (int m = 0; m < 32; m++) a32[m] += xv * xr[m];
            }
            const int b = blk * 4 + bb;
            const int mtile = b >> 6, rowl = b & 63;
            const size_t base = (size_t)mtile * 524288 + (size_t)(h >> 2) * 16384
                              + (size_t)((h >> 1) & 1) * 8192 + (size_t)rowl * 128;
            const uint32_t sw = (uint32_t)(rowl & 7) << 4;
#pragma unroll
            for (int g16 = 0; g16 < 4; g16++) {
                uint32_t w[4];
#pragma unroll
                for (int e = 0; e < 4; e++) {
                    __half2 h2 = __floats2half2_rn(a32[g16 * 8 + e * 2],
                                                   a32[g16 * 8 + e * 2 + 1]);
                    w[e] = h2u(h2);
                }
                const uint32_t off = ((uint32_t)((h & 1) * 64 + g16 * 16)) ^ sw;
                *reinterpret_cast<uint4*>(img + base + off) = make_uint4(w[0], w[1], w[2], w[3]);
            }
        }
    }
}

// -------- l2_gemm: [1024,4096]@[4096,128], 16-way split-K, atomic out -------
__global__ __launch_bounds__(256, 2)
void l2_gemm(float* __restrict__ out)
{
    extern __shared__ char smem[];
    const uint32_t sb = smem_u32(smem);
    const int tid  = threadIdx.x;
    const int wid  = tid >> 5;
    const int lane = tid & 31;
    const int mtile = blockIdx.x >> 4;   // 0..15
    const int kg    = blockIdx.x & 15;   // 0..15 (2 chunks each)

    const char* Asrc = reinterpret_cast<const char*>(g_xlB)
                     + (size_t)mtile * 524288 + (size_t)kg * 2 * 16384;
    const char* Bsrc = reinterpret_cast<const char*>(g_Wt + 655360)
                     + (size_t)kg * 2 * 32768;

    if (tid == 0) {
        MBAR_INIT(sb + OFF2_MBAR + 0, 1);
        MBAR_INIT(sb + OFF2_MBAR + 8, 1);
    }
    __syncthreads();
    if (tid == 0) {   // both stages up-front: zero wait-chain
#pragma unroll
        for (int i = 0; i < 2; i++) {
            MBAR_EXPECT_TX(sb + OFF2_MBAR + 8 * i, 49152);
            BULK_CP(sb + OFF2_A + i * 16384, Asrc + (size_t)i * 16384,
                    16384, sb + OFF2_MBAR + 8 * i);
            BULK_CP(sb + OFF2_B + i * 32768, Bsrc + (size_t)i * 32768,
                    32768, sb + OFF2_MBAR + 8 * i);
        }
    }

    const int mg = wid >> 2, ng = wid & 3;
    const int rlow = lane >> 2;
    const int g = lane >> 3;

    float acc[2][4][4];
#pragma unroll
    for (int mt = 0; mt < 2; mt++)
#pragma unroll
        for (int nt = 0; nt < 4; nt++)
#pragma unroll
            for (int e = 0; e < 4; e++) acc[mt][nt][e] = 0.f;

#pragma unroll
    for (int i = 0; i < 2; i++) {
        MBAR_WAIT(sb + OFF2_MBAR + 8 * i, 0);
        const uint32_t abase = sb + OFF2_A + i * 16384;
        const uint32_t bbase = sb + OFF2_B + i * 32768;
#pragma unroll
        for (int ks = 0; ks < 8; ks++) {
            const int k0 = ks * 16;
            uint32_t afr[2][4];
#pragma unroll
            for (int mt = 0; mt < 2; mt++) {
                const int ar = mg * 32 + mt * 16 + (g & 1) * 8 + (lane & 7);
                const int ak = k0 + (g >> 1) * 8;
                ldsm4(afr[mt], abase + (ak >> 6) * 8192 + ar * 128
                               + (((uint32_t)(ak & 63) * 2) ^ ((ar & 7) << 4)));
            }
            uint32_t bfr[4][2];
#pragma unroll
            for (int bt = 0; bt < 2; bt++) {
                const int br = ng * 32 + bt * 16 + (g >> 1) * 8 + (lane & 7);
                const int bk = k0 + (g & 1) * 8;
                uint32_t r[4];
                ldsm4(r, bbase + (bk >> 6) * 16384 + br * 128
                         + (((uint32_t)(bk & 63) * 2) ^ ((br & 7) << 4)));
                bfr[bt * 2][0] = r[0]; bfr[bt * 2][1] = r[1];
                bfr[bt * 2 + 1][0] = r[2]; bfr[bt * 2 + 1][1] = r[3];
            }
#pragma unroll
            for (int mt = 0; mt < 2; mt++)
#pragma unroll
                for (int nt = 0; nt < 4; nt++)
                    mma16816(acc[mt][nt], afr[mt], bfr[nt]);
        }
    }

    // accumulate split-K contribution directly into out cols [256,384)
#pragma unroll
    for (int mt = 0; mt < 2; mt++) {
        const int b = mtile * 64 + mg * 32 + mt * 16 + rlow;
#pragma unroll
        for (int nt = 0; nt < 4; nt++) {
            const int j0 = ng * 32 + nt * 8 + (lane & 3) * 2;
            float* d0 = out + (size_t)b * OUTW + 256 + j0;
            float* d1 = out + (size_t)(b + 8) * OUTW + 256 + j0;
            atomicAdd(d0,     acc[mt][nt][0]);
            atomicAdd(d0 + 1, acc[mt][nt][1]);
            atomicAdd(d1,     acc[mt][nt][2]);
            atomicAdd(d1 + 1, acc[mt][nt][3]);
        }
    }
}

// ---------------- host ----------------
extern "C" void kernel_launch(void* const* d_in, const int* in_sizes, int n_in,
                              void* d_out, int out_size)
{
    const float* inputs = (const float*)d_in[0];
    const float* W0     = (const float*)d_in[1];
    const float* b0     = (const float*)d_in[2];
    const float* W1     = (const float*)d_in[3];
    const float* b1     = (const float*)d_in[4];
    const float* W2     = (const float*)d_in[5];
    const float* b2     = (const float*)d_in[6];
    float* out = (float*)d_out;

    cudaFuncSetAttribute(cin01,   cudaFuncAttributeMaxDynamicSharedMemorySize, SMEM_TOTAL);
    cudaFuncSetAttribute(l2_gemm, cudaFuncAttributeMaxDynamicSharedMemorySize, SMEM2_TOTAL);

    wprep_all<<<416, 256>>>(W0, W1, W2, b2, out);

    cin01<<<NCTA, NTHR, SMEM_TOTAL>>>(inputs, b0, b1, out);
    l2_gemm<<<256, 256, SMEM2_TOTAL>>>(out);
}